// round 1
// baseline (speedup 1.0000x reference)
#include <cuda_runtime.h>
#include <cstdint>

// Problem constants (fixed shapes)
#define B_    16
#define T_    2048
#define P_    64      // channels == number of nets
#define LAG_  5
#define H0_   32
#define H1_   32
#define TOUT_ (T_ - LAG_ + 1)   // 2044

#define TILE_  256
#define NT_    128
#define XROW_  262              // smem row stride for Xs (even -> float2 aligned)

// Pre-transposed weight scratch (allowed: __device__ globals, no allocation)
__device__ float g_W0t[P_ * (P_ * LAG_) * H0_];  // [n][c*LAG+l][h]  (h contiguous)
__device__ float g_W1t[P_ * H0_ * H1_];          // [n][i][o]        (o contiguous)

typedef unsigned long long ull;

__device__ __forceinline__ ull pk(float lo, float hi) {
    ull r;
    asm("mov.b64 %0, {%1, %2};" : "=l"(r) : "f"(lo), "f"(hi));
    return r;
}
__device__ __forceinline__ void upk(ull v, float& lo, float& hi) {
    asm("mov.b64 {%0, %1}, %2;" : "=f"(lo), "=f"(hi) : "l"(v));
}
__device__ __forceinline__ ull fma2(ull a, ull b, ull c) {
    ull d;
    asm("fma.rn.f32x2 %0, %1, %2, %3;" : "=l"(d) : "l"(a), "l"(b), "l"(c));
    return d;
}

// ---------------------------------------------------------------------------
// Prologue: transpose W0 -> [n][c*LAG+l][h], W1 -> [n][i][o]
// ---------------------------------------------------------------------------
__global__ void prep_weights(const float* __restrict__ W0,
                             const float* __restrict__ W1) {
    const int stride = gridDim.x * blockDim.x;
    const int tid0 = blockIdx.x * blockDim.x + threadIdx.x;

    const int TOT0 = P_ * (P_ * LAG_) * H0_;  // 64*320*32
    for (int d = tid0; d < TOT0; d += stride) {
        int n  = d / ((P_ * LAG_) * H0_);
        int r  = d - n * ((P_ * LAG_) * H0_);
        int cl = r >> 5;
        int h  = r & 31;
        int c  = cl / LAG_;
        int l  = cl - c * LAG_;
        g_W0t[d] = W0[(((n * H0_ + h) * P_ + c) * LAG_) + l];
    }
    const int TOT1 = P_ * H0_ * H1_;  // 64*32*32
    for (int d = tid0; d < TOT1; d += stride) {
        int n = d >> 10;
        int r = d & 1023;
        int i = r >> 5;
        int o = r & 31;
        g_W1t[d] = W1[((n * H1_ + o) * H0_) + i];
    }
}

// ---------------------------------------------------------------------------
// Head (layer1 + layer2) for one timestep, from layer0 accumulators
// ---------------------------------------------------------------------------
__device__ __forceinline__ float mlp_head(const ull (&acc)[16],
                                          const float* __restrict__ W1s,
                                          const float* __restrict__ bss) {
    // ReLU(layer0)
    float a[H0_];
#pragma unroll
    for (int q = 0; q < 16; ++q) {
        float lo, hi;
        upk(acc[q], lo, hi);
        a[2 * q]     = fmaxf(lo, 0.0f);
        a[2 * q + 1] = fmaxf(hi, 0.0f);
    }
    // layer1: c2[o] = b1[o] + sum_i a[i] * W1[n][o][i]   (W1s is [i][o])
    ull c2[16];
#pragma unroll
    for (int q = 0; q < 16; ++q)
        c2[q] = pk(bss[32 + 2 * q], bss[32 + 2 * q + 1]);
#pragma unroll 8
    for (int i = 0; i < H0_; ++i) {
        ull xa = pk(a[i], a[i]);
        const ulonglong2* wp1 = (const ulonglong2*)(W1s + i * H1_);
#pragma unroll
        for (int q = 0; q < 8; ++q) {
            ulonglong2 w = wp1[q];
            c2[2 * q]     = fma2(xa, w.x, c2[2 * q]);
            c2[2 * q + 1] = fma2(xa, w.y, c2[2 * q + 1]);
        }
    }
    // layer2: r = b2 + sum_o relu(c2[o]) * W2[n][o]
    float r = bss[96];
#pragma unroll
    for (int q = 0; q < 16; ++q) {
        float lo, hi;
        upk(c2[q], lo, hi);
        r = fmaf(fmaxf(lo, 0.0f), bss[64 + 2 * q], r);
        r = fmaf(fmaxf(hi, 0.0f), bss[64 + 2 * q + 1], r);
    }
    return r;
}

// ---------------------------------------------------------------------------
// Main kernel: one block per (t-tile, net, batch). 128 threads, 2 t each.
// ---------------------------------------------------------------------------
__global__ __launch_bounds__(NT_, 2)
void cmlp_kernel(const float* __restrict__ X,
                 const float* __restrict__ b0,
                 const float* __restrict__ b1,
                 const float* __restrict__ W2,
                 const float* __restrict__ b2,
                 float* __restrict__ out) {
    extern __shared__ float smem[];
    float* W0s = smem;                       // 10240 floats: [c*LAG+l][h]
    float* W1s = smem + 10240;               // 1024 floats:  [i][o]
    float* Xs  = smem + 11264;               // 64 * XROW_ floats: [c][t_local]
    float* bss = smem + 11264 + P_ * XROW_;  // b0[32] | b1[32] | W2[32] | b2

    const int t0  = blockIdx.x * TILE_;
    const int n   = blockIdx.y;
    const int bb  = blockIdx.z;
    const int tid = threadIdx.x;

    // --- load pre-transposed weights (coalesced float4) ---
    {
        const float4* s0 = (const float4*)(g_W0t + n * (P_ * LAG_ * H0_));
        float4* d0 = (float4*)W0s;
#pragma unroll 4
        for (int i = tid; i < (P_ * LAG_ * H0_) / 4; i += NT_) d0[i] = s0[i];
        const float4* s1 = (const float4*)(g_W1t + n * (H0_ * H1_));
        float4* d1 = (float4*)W1s;
#pragma unroll 2
        for (int i = tid; i < (H0_ * H1_) / 4; i += NT_) d1[i] = s1[i];
        if (tid < 32) {
            bss[tid]      = b0[n * H0_ + tid];
            bss[32 + tid] = b1[n * H1_ + tid];
            bss[64 + tid] = W2[n * H1_ + tid];
        }
        if (tid == 0) bss[96] = b2[n];
    }

    // --- stage X tile transposed: Xs[c][i] = X[bb][t0+i][c], i in [0, 260) ---
    {
        const int NI = TILE_ + LAG_ - 1;  // 260
        for (int m = tid; m < NI * (P_ / 4); m += NT_) {
            int i  = m >> 4;          // 0..259
            int c4 = m & 15;          // 0..15
            int t  = t0 + i;
            float4 v = make_float4(0.f, 0.f, 0.f, 0.f);
            if (t < T_) v = *(const float4*)(X + ((size_t)bb * T_ + t) * P_ + 4 * c4);
            Xs[(4 * c4 + 0) * XROW_ + i] = v.x;
            Xs[(4 * c4 + 1) * XROW_ + i] = v.y;
            Xs[(4 * c4 + 2) * XROW_ + i] = v.z;
            Xs[(4 * c4 + 3) * XROW_ + i] = v.w;
        }
    }
    __syncthreads();

    const int tt    = 2 * tid;       // local time
    const int tglob = t0 + tt;
    if (tglob >= TOUT_) return;      // whole-thread early exit (after barrier)

    // --- layer0: acc[t][h] = b0[h] + sum_{c,l} X[t+l][c] * W0[h][c][l] ---
    ull acc0[16], acc1[16];
#pragma unroll
    for (int q = 0; q < 16; ++q) {
        ull bv = pk(bss[2 * q], bss[2 * q + 1]);
        acc0[q] = bv;
        acc1[q] = bv;
    }

#pragma unroll 2
    for (int c = 0; c < P_; ++c) {
        const float* xr = Xs + c * XROW_ + tt;
        float2 x01 = *(const float2*)(xr);
        float2 x23 = *(const float2*)(xr + 2);
        float2 x45 = *(const float2*)(xr + 4);
        float xv[6] = {x01.x, x01.y, x23.x, x23.y, x45.x, x45.y};
        const ulonglong2* wp = (const ulonglong2*)(W0s + c * (LAG_ * H0_));
#pragma unroll
        for (int l = 0; l < LAG_; ++l) {
            ull xa = pk(xv[l], xv[l]);
            ull xb = pk(xv[l + 1], xv[l + 1]);
#pragma unroll
            for (int q = 0; q < 8; ++q) {
                ulonglong2 w = wp[l * 8 + q];
                acc0[2 * q]     = fma2(xa, w.x, acc0[2 * q]);
                acc0[2 * q + 1] = fma2(xa, w.y, acc0[2 * q + 1]);
                acc1[2 * q]     = fma2(xb, w.x, acc1[2 * q]);
                acc1[2 * q + 1] = fma2(xb, w.y, acc1[2 * q + 1]);
            }
        }
    }

    // --- layers 1+2 per timestep, then store ---
    float r0 = mlp_head(acc0, W1s, bss);
    out[((size_t)bb * TOUT_ + tglob) * P_ + n] = r0;
    if (tglob + 1 < TOUT_) {
        float r1 = mlp_head(acc1, W1s, bss);
        out[((size_t)bb * TOUT_ + tglob + 1) * P_ + n] = r1;
    }
}

// ---------------------------------------------------------------------------
// Launch
// ---------------------------------------------------------------------------
extern "C" void kernel_launch(void* const* d_in, const int* in_sizes, int n_in,
                              void* d_out, int out_size) {
    const float* X  = (const float*)d_in[0];
    const float* W0 = (const float*)d_in[1];
    const float* b0 = (const float*)d_in[2];
    const float* W1 = (const float*)d_in[3];
    const float* b1 = (const float*)d_in[4];
    const float* W2 = (const float*)d_in[5];
    const float* b2 = (const float*)d_in[6];
    float* out = (float*)d_out;

    const int smem_bytes = (11264 + P_ * XROW_ + 128) * (int)sizeof(float);  // ~110.5 KB
    cudaFuncSetAttribute(cmlp_kernel, cudaFuncAttributeMaxDynamicSharedMemorySize,
                         smem_bytes);

    prep_weights<<<256, 256>>>(W0, W1);

    dim3 grid((TOUT_ + TILE_ - 1) / TILE_, P_, B_);  // (8, 64, 16)
    cmlp_kernel<<<grid, NT_, smem_bytes>>>(X, b0, b1, W2, b2, out);
}